// round 10
// baseline (speedup 1.0000x reference)
#include <cuda_runtime.h>
#include <math.h>

// ============================================================================
// EquivariantDecoder — R8 resubmit (infra failure last round, never measured).
//   phase5: TB=8, NT=128 (32 lanes = out-cols, 4 warps = row-pairs).
//   - weights UN-duplicated: LDG.64 float2 (2 wf) + broadcast-pack movs
//   - x loaded as paired LDS.128 uniform broadcasts (1 wf per 2 m-values)
//   gate/prep/layer4 kernels: unchanged from passing R7.
// ============================================================================

typedef unsigned long long u64;

#define BROWS 16384
#define HD    1856

__device__ __forceinline__ u64 ffma2(u64 a, u64 b, u64 c) {
    u64 d;
    asm("fma.rn.f32x2 %0, %1, %2, %3;" : "=l"(d) : "l"(a), "l"(b), "l"(c));
    return d;
}
__device__ __forceinline__ u64 pk1(float w) {
    u64 r;
    asm("mov.b64 %0, {%1, %1};" : "=l"(r) : "f"(w));
    return r;
}
__device__ __forceinline__ u64 pk2(float a, float b) {
    u64 r;
    asm("mov.b64 %0, {%1, %2};" : "=l"(r) : "f"(a), "f"(b));
    return r;
}
__device__ __forceinline__ float2 upk(u64 v) {
    float2 r;
    asm("mov.b64 {%0, %1}, %2;" : "=f"(r.x), "=f"(r.y) : "l"(v));
    return r;
}
__device__ __forceinline__ float sigf(float x) { return 1.0f / (1.0f + __expf(-x)); }

// ---- static device buffers (no allocation allowed) -------------------------
__device__ __align__(16) float g_h1[(size_t)BROWS * HD];
__device__ __align__(16) float g_h2[(size_t)BROWS * HD];
__device__ __align__(16) float g_gates[(size_t)BROWS * 256];
__device__ __align__(16) float g_w1d[212992];   // duplicated weights (gate kernels)
__device__ __align__(16) float g_w2d[65536];
__device__ __align__(16) float g_w3d[65536];

__global__ void prep_kernel(const float* __restrict__ w1,
                            const float* __restrict__ w2,
                            const float* __restrict__ w3) {
    int k = blockIdx.x * 256 + threadIdx.x;
    if (k < 106496) { float v = w1[k]; g_w1d[2 * k] = v; g_w1d[2 * k + 1] = v; }
    if (k < 32768)  { float v = w2[k]; g_w2d[2 * k] = v; g_w2d[2 * k + 1] = v;
                      float u = w3[k]; g_w3d[2 * k] = u; g_w3d[2 * k + 1] = u; }
}

// ============================================================================
// gate_kernel — unchanged (passing since R4).
// ============================================================================
template <int MI0>
__global__ __launch_bounds__(160) void gate_kernel(
    const float* __restrict__ xin, int in_dim,
    const float* __restrict__ wdA, const float* __restrict__ wdB,
    float* __restrict__ hout, float* __restrict__ gates, float sc)
{
    constexpr int STRIDE = 34;
    __shared__ __align__(16) float sxs[MI0 * STRIDE];
    u64* sx64 = (u64*)sxs;

    const int tid = threadIdx.x;
    const int oc = tid % 40;
    const int rg = tid / 40;
    const int row0 = blockIdx.x * 32;

    for (int r = 0; r < 32; r++) {
        const float4* s4 = (const float4*)(xin + (size_t)(row0 + r) * in_dim);
        for (int c4 = tid; c4 < MI0 / 4; c4 += 160) {
            float4 v = __ldg(s4 + c4);
            sxs[(4 * c4 + 0) * STRIDE + r] = v.x;
            sxs[(4 * c4 + 1) * STRIDE + r] = v.y;
            sxs[(4 * c4 + 2) * STRIDE + r] = v.z;
            sxs[(4 * c4 + 3) * STRIDE + r] = v.w;
        }
    }
    __syncthreads();

    u64 acc[8][4];
#pragma unroll
    for (int k = 0; k < 8; k++)
#pragma unroll
        for (int j = 0; j < 4; j++) acc[k][j] = 0ull;

    const bool is_silu = (oc < 8);
    if (is_silu) {
        const ulonglong2* wr = (const ulonglong2*)wdA + oc * 4;   // dup row = 32 ull2
#pragma unroll 2
        for (int i = 0; i < MI0; i++) {
            u64 w[8];
#pragma unroll
            for (int q = 0; q < 4; q++) {
                ulonglong2 t = __ldg(wr + i * 32 + q);
                w[2 * q] = t.x; w[2 * q + 1] = t.y;
            }
#pragma unroll
            for (int j = 0; j < 4; j++) {
                u64 xv = sx64[i * 17 + (rg * 4 + j)];
#pragma unroll
                for (int k = 0; k < 8; k++) acc[k][j] = ffma2(xv, w[k], acc[k][j]);
            }
        }
    } else {
        const ulonglong2* wr = (const ulonglong2*)wdB + (oc - 8) * 4;  // dup row = 128 ull2
#pragma unroll 2
        for (int i = 0; i < MI0; i++) {
            u64 w[8];
#pragma unroll
            for (int q = 0; q < 4; q++) {
                ulonglong2 t = __ldg(wr + i * 128 + q);
                w[2 * q] = t.x; w[2 * q + 1] = t.y;
            }
#pragma unroll
            for (int j = 0; j < 4; j++) {
                u64 xv = sx64[i * 17 + (rg * 4 + j)];
#pragma unroll
                for (int k = 0; k < 8; k++) acc[k][j] = ffma2(xv, w[k], acc[k][j]);
            }
        }
    }

    if (is_silu) {
        const int o0 = oc * 8;
#pragma unroll
        for (int j = 0; j < 4; j++) {
            int r0 = row0 + (rg * 4 + j) * 2;
            float e0[8], e1[8];
#pragma unroll
            for (int k = 0; k < 8; k++) {
                float2 a = upk(acc[k][j]);
                float z0 = a.x * sc, z1 = a.y * sc;
                e0[k] = z0 * sigf(z0);
                e1[k] = z1 * sigf(z1);
            }
            float4* d0 = (float4*)(hout + (size_t)r0 * HD + o0);
            float4* d1 = (float4*)(hout + (size_t)(r0 + 1) * HD + o0);
            d0[0] = make_float4(e0[0], e0[1], e0[2], e0[3]);
            d0[1] = make_float4(e0[4], e0[5], e0[6], e0[7]);
            d1[0] = make_float4(e1[0], e1[1], e1[2], e1[3]);
            d1[1] = make_float4(e1[4], e1[5], e1[6], e1[7]);
        }
    } else {
        const int o0 = (oc - 8) * 8;
#pragma unroll
        for (int j = 0; j < 4; j++) {
            size_t bp = (size_t)(row0 / 2 + rg * 4 + j);
            u64 o[8];
#pragma unroll
            for (int k = 0; k < 8; k++) {
                float2 a = upk(acc[k][j]);
                o[k] = pk2(sigf(a.x * sc), sigf(a.y * sc));
            }
            ulonglong2* gp = (ulonglong2*)gates + (bp * 256 + o0) / 2;
#pragma unroll
            for (int q = 0; q < 4; q++)
                gp[q] = make_ulonglong2(o[2 * q], o[2 * q + 1]);
        }
    }
}

// ============================================================================
// phase5_kernel<MI,NM,MO>: y[b,o,m] = sc * g[b,o] * sum_i x[b,i,m] w[i,o]
//   NT=128: oc = tid&31, rp = tid>>5 (warp-uniform -> broadcast LDS)
//   OPT = MO/32. Weights UN-dup (LDG.64/32) + pk1; x in smem padded to NMp
//   u64 per i-block so m-pairs load as one LDS.128 broadcast (1 wf).
// ============================================================================
template <int MI, int NM, int MO>
__global__ __launch_bounds__(128, 8) void phase5_kernel(
    const float* __restrict__ xin, int in_dim, int in_off,
    const float* __restrict__ w, const float* __restrict__ gates,
    int goff, float* __restrict__ hout, int hoff, float sc)
{
    constexpr int OPT = MO / 32;           // 2 (MO=64) or 1 (MO=32)
    constexpr int FEATS = MI * NM;
    constexpr int NMp = (NM + 1) & ~1;     // even -> 16B-aligned i-blocks
    constexpr int ROWU = MI * NMp;         // u64 per row-pair (even)
    constexpr int OUTLEN = MO * NM;

    __shared__ __align__(16) u64 sx[4 * ROWU];
    float* sxf = (float*)sx;

    const int tid = threadIdx.x;
    const int oc = tid & 31;
    const int rp = tid >> 5;
    const int row0 = blockIdx.x * 8;

    // ---- load x tile: row-pairs in u64 lanes, i-blocks padded to NMp ----
    for (int r = 0; r < 8; r++) {
        const float* src = xin + (size_t)(row0 + r) * in_dim + in_off;
        float* dst = (float*)(sx + (r >> 1) * ROWU) + (r & 1);
        for (int f = tid; f < FEATS; f += 128) {
            int i = f / NM;
            int m = f - i * NM;
            dst[2 * (i * NMp + m)] = __ldg(src + f);
        }
    }
    __syncthreads();

    u64 acc[OPT][NM];
#pragma unroll
    for (int j = 0; j < OPT; j++)
#pragma unroll
        for (int m = 0; m < NM; m++) acc[j][m] = 0ull;

    const u64* xp = sx + rp * ROWU;

    if (OPT == 2) {
        const float2* wv = (const float2*)w + oc;   // row = MO/2 = 32 float2
#pragma unroll 2
        for (int i = 0; i < MI; i++) {
            float2 t = __ldg(wv + i * 32);
            u64 w0 = pk1(t.x), w1 = pk1(t.y);
            const u64* xb = xp + i * NMp;
#pragma unroll
            for (int m = 0; m + 1 < NM; m += 2) {
                ulonglong2 p = *(const ulonglong2*)(xb + m);   // LDS.128 bcast
                acc[0][m]     = ffma2(p.x, w0, acc[0][m]);
                acc[1][m]     = ffma2(p.x, w1, acc[1][m]);
                acc[0][m + 1] = ffma2(p.y, w0, acc[0][m + 1]);
                acc[1][m + 1] = ffma2(p.y, w1, acc[1][m + 1]);
            }
            {   // odd tail (NM is odd for all phases)
                u64 xv = xb[NM - 1];
                acc[0][NM - 1] = ffma2(xv, w0, acc[0][NM - 1]);
                acc[1][NM - 1] = ffma2(xv, w1, acc[1][NM - 1]);
            }
        }
    } else {
        const float* wv = w + oc;                   // row = MO = 32 floats
#pragma unroll 2
        for (int i = 0; i < MI; i++) {
            u64 w0 = pk1(__ldg(wv + i * 32));
            const u64* xb = xp + i * NMp;
#pragma unroll
            for (int m = 0; m + 1 < NM; m += 2) {
                ulonglong2 p = *(const ulonglong2*)(xb + m);
                acc[0][m]     = ffma2(p.x, w0, acc[0][m]);
                acc[0][m + 1] = ffma2(p.y, w0, acc[0][m + 1]);
            }
            acc[0][NM - 1] = ffma2(xb[NM - 1], w0, acc[0][NM - 1]);
        }
    }

    // gates (row-pair packed)
    u64 g[OPT];
    const u64* gp = (const u64*)gates + (size_t)(row0 / 2 + rp) * 256 + goff + oc * OPT;
#pragma unroll
    for (int j = 0; j < OPT; j++) g[j] = __ldg(gp + j);

    __syncthreads();   // done reading x; reuse smem as output stage

#pragma unroll
    for (int j = 0; j < OPT; j++) {
        float2 gg = upk(g[j]);
#pragma unroll
        for (int m = 0; m < NM; m++) {
            float2 a = upk(acc[j][m]);
            int col = (oc * OPT + j) * NM + m;
            sxf[(2 * rp) * OUTLEN + col]     = a.x * sc * gg.x;
            sxf[(2 * rp + 1) * OUTLEN + col] = a.y * sc * gg.y;
        }
    }
    __syncthreads();

    for (int r = 0; r < 8; r++) {
        float4* d = (float4*)(hout + (size_t)(row0 + r) * HD + hoff);
        const float4* s = (const float4*)(sxf + r * OUTLEN);
        for (int c = tid; c < OUTLEN / 4; c += 128) d[c] = s[c];
    }
}

// ============================================================================
// layer4: final projection HID -> 49 per row (unchanged)
// ============================================================================
__global__ __launch_bounds__(256) void layer4_kernel(
    const float* __restrict__ h, const float* __restrict__ w4,
    float* __restrict__ out)
{
    const int warp = threadIdx.x >> 5;
    const int lane = threadIdx.x & 31;
    const int row  = blockIdx.x * 8 + warp;

    const float* hr = h + (size_t)row * HD;

    const int MI[7]   = {64, 64, 64, 32, 32, 32, 32};
    const int XOFF[7] = {0, 64, 256, 576, 800, 1088, 1440};
    const int WOFF[7] = {0, 64, 128, 192, 224, 256, 288};
    const int OOFF[7] = {0, 1, 4, 9, 16, 25, 36};

#pragma unroll
    for (int l = 0; l < 7; l++) {
        const int nm = 2 * l + 1;
        const int mi = MI[l];
        const float sc = rsqrtf((float)mi);
        for (int m = 0; m < nm; m++) {
            float s = 0.0f;
            for (int i = lane; i < mi; i += 32)
                s += hr[XOFF[l] + i * nm + m] * __ldg(w4 + WOFF[l] + i);
#pragma unroll
            for (int off = 16; off; off >>= 1)
                s += __shfl_xor_sync(0xFFFFFFFFu, s, off);
            if (lane == 0)
                out[(size_t)row * 49 + OOFF[l] + m] = s * sc;
        }
    }
}

// ---- launch ----------------------------------------------------------------
extern "C" void kernel_launch(void* const* d_in, const int* in_sizes, int n_in,
                              void* d_out, int out_size)
{
    const float* v  = (const float*)d_in[0];
    const float* w1 = (const float*)d_in[1];
    const float* w2 = (const float*)d_in[2];
    const float* w3 = (const float*)d_in[3];
    const float* w4 = (const float*)d_in[4];
    float* out = (float*)d_out;

    float *h1, *h2, *gt, *w1d, *w2d, *w3d;
    cudaGetSymbolAddress((void**)&h1,  g_h1);
    cudaGetSymbolAddress((void**)&h2,  g_h2);
    cudaGetSymbolAddress((void**)&gt,  g_gates);
    cudaGetSymbolAddress((void**)&w1d, g_w1d);
    cudaGetSymbolAddress((void**)&w2d, g_w2d);
    cudaGetSymbolAddress((void**)&w3d, g_w3d);

    const float s256 = 1.0f / sqrtf(256.0f);
    const float s128 = 1.0f / sqrtf(128.0f);
    const float s64  = 1.0f / sqrtf(64.0f);
    const float s32  = 1.0f / sqrtf(32.0f);

    prep_kernel<<<416, 256>>>(w1, w2, w3);

    const int G32 = BROWS / 32;   // 512  (gate kernels)
    const int G8  = BROWS / 8;    // 2048 (phase kernels)

    // ---- layer 1: v(3840) -> h1   (phase weights UN-duplicated)
    gate_kernel<256><<<G32, 160>>>(v, 3840, w1d, w1d + 16384 * 2, h1, gt, s256);
    phase5_kernel<128,  3, 64><<<G8, 128>>>(v, 3840,  256, w1 +  81920, gt,   0, h1,   64, s128);
    phase5_kernel<128,  5, 64><<<G8, 128>>>(v, 3840,  640, w1 +  90112, gt,  64, h1,  256, s128);
    phase5_kernel< 64,  7, 32><<<G8, 128>>>(v, 3840, 1280, w1 +  98304, gt, 128, h1,  576, s64);
    phase5_kernel< 64,  9, 32><<<G8, 128>>>(v, 3840, 1728, w1 + 100352, gt, 160, h1,  800, s64);
    phase5_kernel< 64, 11, 32><<<G8, 128>>>(v, 3840, 2304, w1 + 102400, gt, 192, h1, 1088, s64);
    phase5_kernel< 64, 13, 32><<<G8, 128>>>(v, 3840, 3008, w1 + 104448, gt, 224, h1, 1440, s64);

    // ---- layer 2: h1 -> h2
    gate_kernel<64><<<G32, 160>>>(h1, HD, w2d, w2d + 4096 * 2, h2, gt, s64);
    phase5_kernel<64,  3, 64><<<G8, 128>>>(h1, HD,   64, w2 + 20480, gt,   0, h2,   64, s64);
    phase5_kernel<64,  5, 64><<<G8, 128>>>(h1, HD,  256, w2 + 24576, gt,  64, h2,  256, s64);
    phase5_kernel<32,  7, 32><<<G8, 128>>>(h1, HD,  576, w2 + 28672, gt, 128, h2,  576, s32);
    phase5_kernel<32,  9, 32><<<G8, 128>>>(h1, HD,  800, w2 + 29696, gt, 160, h2,  800, s32);
    phase5_kernel<32, 11, 32><<<G8, 128>>>(h1, HD, 1088, w2 + 30720, gt, 192, h2, 1088, s32);
    phase5_kernel<32, 13, 32><<<G8, 128>>>(h1, HD, 1440, w2 + 31744, gt, 224, h2, 1440, s32);

    // ---- layer 3: h2 -> h1
    gate_kernel<64><<<G32, 160>>>(h2, HD, w3d, w3d + 4096 * 2, h1, gt, s64);
    phase5_kernel<64,  3, 64><<<G8, 128>>>(h2, HD,   64, w3 + 20480, gt,   0, h1,   64, s64);
    phase5_kernel<64,  5, 64><<<G8, 128>>>(h2, HD,  256, w3 + 24576, gt,  64, h1,  256, s64);
    phase5_kernel<32,  7, 32><<<G8, 128>>>(h2, HD,  576, w3 + 28672, gt, 128, h1,  576, s32);
    phase5_kernel<32,  9, 32><<<G8, 128>>>(h2, HD,  800, w3 + 29696, gt, 160, h1,  800, s32);
    phase5_kernel<32, 11, 32><<<G8, 128>>>(h2, HD, 1088, w3 + 30720, gt, 192, h1, 1088, s32);
    phase5_kernel<32, 13, 32><<<G8, 128>>>(h2, HD, 1440, w3 + 31744, gt, 224, h1, 1440, s32);

    // ---- layer 4
    layer4_kernel<<<BROWS / 8, 256>>>(h1, w4, out);
}

// round 11
// speedup vs baseline: 1.7162x; 1.7162x over previous
#include <cuda_runtime.h>
#include <math.h>

// ============================================================================
// EquivariantDecoder — R10: R7 baseline + paired LDS.128 x-broadcasts.
//   phase6 = R7 phase3 (dup weights, LDG.128/64, zero pack movs) with the x
//   tile padded so m-pairs read as one LDS.128 uniform broadcast, and a
//   2-way-conflict loader. Gate/prep/layer4 identical to R7 (1219us).
// ============================================================================

typedef unsigned long long u64;

#define BROWS 16384
#define HD    1856

__device__ __forceinline__ u64 ffma2(u64 a, u64 b, u64 c) {
    u64 d;
    asm("fma.rn.f32x2 %0, %1, %2, %3;" : "=l"(d) : "l"(a), "l"(b), "l"(c));
    return d;
}
__device__ __forceinline__ u64 pk2(float a, float b) {
    u64 r;
    asm("mov.b64 %0, {%1, %2};" : "=l"(r) : "f"(a), "f"(b));
    return r;
}
__device__ __forceinline__ float2 upk(u64 v) {
    float2 r;
    asm("mov.b64 {%0, %1}, %2;" : "=f"(r.x), "=f"(r.y) : "l"(v));
    return r;
}
__device__ __forceinline__ float sigf(float x) { return 1.0f / (1.0f + __expf(-x)); }

// ---- static device buffers (no allocation allowed) -------------------------
__device__ __align__(16) float g_h1[(size_t)BROWS * HD];
__device__ __align__(16) float g_h2[(size_t)BROWS * HD];
__device__ __align__(16) float g_gates[(size_t)BROWS * 256];
__device__ __align__(16) float g_w1d[212992];   // duplicated weights
__device__ __align__(16) float g_w2d[65536];
__device__ __align__(16) float g_w3d[65536];

__global__ void prep_kernel(const float* __restrict__ w1,
                            const float* __restrict__ w2,
                            const float* __restrict__ w3) {
    int k = blockIdx.x * 256 + threadIdx.x;
    if (k < 106496) { float v = w1[k]; g_w1d[2 * k] = v; g_w1d[2 * k + 1] = v; }
    if (k < 32768)  { float v = w2[k]; g_w2d[2 * k] = v; g_w2d[2 * k + 1] = v;
                      float u = w3[k]; g_w3d[2 * k] = u; g_w3d[2 * k + 1] = u; }
}

// ============================================================================
// gate_kernel — unchanged (passing since R4).
// ============================================================================
template <int MI0>
__global__ __launch_bounds__(160) void gate_kernel(
    const float* __restrict__ xin, int in_dim,
    const float* __restrict__ wdA, const float* __restrict__ wdB,
    float* __restrict__ hout, float* __restrict__ gates, float sc)
{
    constexpr int STRIDE = 34;
    __shared__ __align__(16) float sxs[MI0 * STRIDE];
    u64* sx64 = (u64*)sxs;

    const int tid = threadIdx.x;
    const int oc = tid % 40;
    const int rg = tid / 40;
    const int row0 = blockIdx.x * 32;

    for (int r = 0; r < 32; r++) {
        const float4* s4 = (const float4*)(xin + (size_t)(row0 + r) * in_dim);
        for (int c4 = tid; c4 < MI0 / 4; c4 += 160) {
            float4 v = __ldg(s4 + c4);
            sxs[(4 * c4 + 0) * STRIDE + r] = v.x;
            sxs[(4 * c4 + 1) * STRIDE + r] = v.y;
            sxs[(4 * c4 + 2) * STRIDE + r] = v.z;
            sxs[(4 * c4 + 3) * STRIDE + r] = v.w;
        }
    }
    __syncthreads();

    u64 acc[8][4];
#pragma unroll
    for (int k = 0; k < 8; k++)
#pragma unroll
        for (int j = 0; j < 4; j++) acc[k][j] = 0ull;

    const bool is_silu = (oc < 8);
    if (is_silu) {
        const ulonglong2* wr = (const ulonglong2*)wdA + oc * 4;   // dup row = 32 ull2
#pragma unroll 2
        for (int i = 0; i < MI0; i++) {
            u64 w[8];
#pragma unroll
            for (int q = 0; q < 4; q++) {
                ulonglong2 t = __ldg(wr + i * 32 + q);
                w[2 * q] = t.x; w[2 * q + 1] = t.y;
            }
#pragma unroll
            for (int j = 0; j < 4; j++) {
                u64 xv = sx64[i * 17 + (rg * 4 + j)];
#pragma unroll
                for (int k = 0; k < 8; k++) acc[k][j] = ffma2(xv, w[k], acc[k][j]);
            }
        }
    } else {
        const ulonglong2* wr = (const ulonglong2*)wdB + (oc - 8) * 4;  // dup row = 128 ull2
#pragma unroll 2
        for (int i = 0; i < MI0; i++) {
            u64 w[8];
#pragma unroll
            for (int q = 0; q < 4; q++) {
                ulonglong2 t = __ldg(wr + i * 128 + q);
                w[2 * q] = t.x; w[2 * q + 1] = t.y;
            }
#pragma unroll
            for (int j = 0; j < 4; j++) {
                u64 xv = sx64[i * 17 + (rg * 4 + j)];
#pragma unroll
                for (int k = 0; k < 8; k++) acc[k][j] = ffma2(xv, w[k], acc[k][j]);
            }
        }
    }

    if (is_silu) {
        const int o0 = oc * 8;
#pragma unroll
        for (int j = 0; j < 4; j++) {
            int r0 = row0 + (rg * 4 + j) * 2;
            float e0[8], e1[8];
#pragma unroll
            for (int k = 0; k < 8; k++) {
                float2 a = upk(acc[k][j]);
                float z0 = a.x * sc, z1 = a.y * sc;
                e0[k] = z0 * sigf(z0);
                e1[k] = z1 * sigf(z1);
            }
            float4* d0 = (float4*)(hout + (size_t)r0 * HD + o0);
            float4* d1 = (float4*)(hout + (size_t)(r0 + 1) * HD + o0);
            d0[0] = make_float4(e0[0], e0[1], e0[2], e0[3]);
            d0[1] = make_float4(e0[4], e0[5], e0[6], e0[7]);
            d1[0] = make_float4(e1[0], e1[1], e1[2], e1[3]);
            d1[1] = make_float4(e1[4], e1[5], e1[6], e1[7]);
        }
    } else {
        const int o0 = (oc - 8) * 8;
#pragma unroll
        for (int j = 0; j < 4; j++) {
            size_t bp = (size_t)(row0 / 2 + rg * 4 + j);
            u64 o[8];
#pragma unroll
            for (int k = 0; k < 8; k++) {
                float2 a = upk(acc[k][j]);
                o[k] = pk2(sigf(a.x * sc), sigf(a.y * sc));
            }
            ulonglong2* gp = (ulonglong2*)gates + (bp * 256 + o0) / 2;
#pragma unroll
            for (int q = 0; q < 4; q++)
                gp[q] = make_ulonglong2(o[2 * q], o[2 * q + 1]);
        }
    }
}

// ============================================================================
// phase6_kernel<MI,NM,MO>: y[b,o,m] = sc * g[b,o] * sum_i x[b,i,m] w[i,o]
//   NT=128: oc = tid&31 (out-cols), rp = tid>>5 (4 row-pairs, TB=8).
//   Weights DUPLICATED (LDG.128/64 -> packed u64, zero movs).
//   x tile padded per i-block to NMp u64 so m-pairs are one LDS.128 bcast.
// ============================================================================
template <int MI, int NM, int MO>
__global__ __launch_bounds__(128, 8) void phase6_kernel(
    const float* __restrict__ xin, int in_dim, int in_off,
    const float* __restrict__ wd, const float* __restrict__ gates,
    int goff, float* __restrict__ hout, int hoff, float sc)
{
    constexpr int OPT = MO / 32;           // 2 (MO=64) or 1 (MO=32)
    constexpr int FEATS = MI * NM;
    constexpr int NMp = (NM + 1) & ~1;     // even u64 per i-block (16B aligned)
    constexpr int ROWU = MI * NMp;         // u64 per row-pair (even)
    constexpr int OUTLEN = MO * NM;

    __shared__ __align__(16) u64 sx[4 * ROWU];
    float* sxf = (float*)sx;

    const int tid = threadIdx.x;
    const int oc = tid & 31;
    const int rp = tid >> 5;
    const int row0 = blockIdx.x * 8;

    // ---- load x tile: float4 LDG, padded scalar STS (2-way conflicts) ----
    for (int r = 0; r < 8; r++) {
        const float4* src = (const float4*)(xin + (size_t)(row0 + r) * in_dim + in_off);
        float* dst = (float*)(sx + (r >> 1) * ROWU) + (r & 1);
        for (int c = tid; c < FEATS / 4; c += 128) {
            float4 v = __ldg(src + c);
            int f = 4 * c;
#pragma unroll
            for (int q = 0; q < 4; q++) {
                int i = (f + q) / NM;
                int m = (f + q) - i * NM;
                dst[2 * (i * NMp + m)] = (&v.x)[q];
            }
        }
    }
    __syncthreads();

    u64 acc[OPT][NM];
#pragma unroll
    for (int j = 0; j < OPT; j++)
#pragma unroll
        for (int m = 0; m < NM; m++) acc[j][m] = 0ull;

    const u64* xp = sx + rp * ROWU;

    if (OPT == 2) {
        // dup row = 64 u64 = 32 ull2; thread oc takes ull2 #oc (LDG.128)
        const ulonglong2* wr = (const ulonglong2*)wd + oc;
#pragma unroll 2
        for (int i = 0; i < MI; i++) {
            ulonglong2 t = __ldg(wr + i * 32);
            const u64* xb = xp + i * NMp;
#pragma unroll
            for (int m = 0; m + 1 < NM; m += 2) {
                ulonglong2 p = *(const ulonglong2*)(xb + m);   // LDS.128 bcast
                acc[0][m]     = ffma2(p.x, t.x, acc[0][m]);
                acc[1][m]     = ffma2(p.x, t.y, acc[1][m]);
                acc[0][m + 1] = ffma2(p.y, t.x, acc[0][m + 1]);
                acc[1][m + 1] = ffma2(p.y, t.y, acc[1][m + 1]);
            }
            {   // odd tail (NM odd for all phases)
                u64 xv = xb[NM - 1];
                acc[0][NM - 1] = ffma2(xv, t.x, acc[0][NM - 1]);
                acc[1][NM - 1] = ffma2(xv, t.y, acc[1][NM - 1]);
            }
        }
    } else {
        // dup row = 32 u64; thread oc takes u64 #oc (LDG.64)
        const u64* wr = (const u64*)wd + oc;
#pragma unroll 2
        for (int i = 0; i < MI; i++) {
            u64 t = __ldg(wr + i * 32);
            const u64* xb = xp + i * NMp;
#pragma unroll
            for (int m = 0; m + 1 < NM; m += 2) {
                ulonglong2 p = *(const ulonglong2*)(xb + m);
                acc[0][m]     = ffma2(p.x, t, acc[0][m]);
                acc[0][m + 1] = ffma2(p.y, t, acc[0][m + 1]);
            }
            acc[0][NM - 1] = ffma2(xb[NM - 1], t, acc[0][NM - 1]);
        }
    }

    // gates (row-pair packed)
    u64 g[OPT];
    const u64* gp = (const u64*)gates + (size_t)(row0 / 2 + rp) * 256 + goff + oc * OPT;
#pragma unroll
    for (int j = 0; j < OPT; j++) g[j] = __ldg(gp + j);

    __syncthreads();   // done reading x; reuse smem as output stage

#pragma unroll
    for (int j = 0; j < OPT; j++) {
        float2 gg = upk(g[j]);
#pragma unroll
        for (int m = 0; m < NM; m++) {
            float2 a = upk(acc[j][m]);
            int col = (oc * OPT + j) * NM + m;
            sxf[(2 * rp) * OUTLEN + col]     = a.x * sc * gg.x;
            sxf[(2 * rp + 1) * OUTLEN + col] = a.y * sc * gg.y;
        }
    }
    __syncthreads();

    for (int r = 0; r < 8; r++) {
        float4* d = (float4*)(hout + (size_t)(row0 + r) * HD + hoff);
        const float4* s = (const float4*)(sxf + r * OUTLEN);
        for (int c = tid; c < OUTLEN / 4; c += 128) d[c] = s[c];
    }
}

// ============================================================================
// layer4: final projection HID -> 49 per row (unchanged)
// ============================================================================
__global__ __launch_bounds__(256) void layer4_kernel(
    const float* __restrict__ h, const float* __restrict__ w4,
    float* __restrict__ out)
{
    const int warp = threadIdx.x >> 5;
    const int lane = threadIdx.x & 31;
    const int row  = blockIdx.x * 8 + warp;

    const float* hr = h + (size_t)row * HD;

    const int MI[7]   = {64, 64, 64, 32, 32, 32, 32};
    const int XOFF[7] = {0, 64, 256, 576, 800, 1088, 1440};
    const int WOFF[7] = {0, 64, 128, 192, 224, 256, 288};
    const int OOFF[7] = {0, 1, 4, 9, 16, 25, 36};

#pragma unroll
    for (int l = 0; l < 7; l++) {
        const int nm = 2 * l + 1;
        const int mi = MI[l];
        const float sc = rsqrtf((float)mi);
        for (int m = 0; m < nm; m++) {
            float s = 0.0f;
            for (int i = lane; i < mi; i += 32)
                s += hr[XOFF[l] + i * nm + m] * __ldg(w4 + WOFF[l] + i);
#pragma unroll
            for (int off = 16; off; off >>= 1)
                s += __shfl_xor_sync(0xFFFFFFFFu, s, off);
            if (lane == 0)
                out[(size_t)row * 49 + OOFF[l] + m] = s * sc;
        }
    }
}

// ---- launch ----------------------------------------------------------------
extern "C" void kernel_launch(void* const* d_in, const int* in_sizes, int n_in,
                              void* d_out, int out_size)
{
    const float* v  = (const float*)d_in[0];
    const float* w1 = (const float*)d_in[1];
    const float* w2 = (const float*)d_in[2];
    const float* w3 = (const float*)d_in[3];
    const float* w4 = (const float*)d_in[4];
    float* out = (float*)d_out;

    float *h1, *h2, *gt, *w1d, *w2d, *w3d;
    cudaGetSymbolAddress((void**)&h1,  g_h1);
    cudaGetSymbolAddress((void**)&h2,  g_h2);
    cudaGetSymbolAddress((void**)&gt,  g_gates);
    cudaGetSymbolAddress((void**)&w1d, g_w1d);
    cudaGetSymbolAddress((void**)&w2d, g_w2d);
    cudaGetSymbolAddress((void**)&w3d, g_w3d);

    const float s256 = 1.0f / sqrtf(256.0f);
    const float s128 = 1.0f / sqrtf(128.0f);
    const float s64  = 1.0f / sqrtf(64.0f);
    const float s32  = 1.0f / sqrtf(32.0f);

    prep_kernel<<<416, 256>>>(w1, w2, w3);

    const int G32 = BROWS / 32;   // 512  (gate kernels)
    const int G8  = BROWS / 8;    // 2048 (phase kernels)

    // ---- layer 1: v(3840) -> h1   (dup weight offsets = 2x original)
    gate_kernel<256><<<G32, 160>>>(v, 3840, w1d, w1d + 16384 * 2, h1, gt, s256);
    phase6_kernel<128,  3, 64><<<G8, 128>>>(v, 3840,  256, w1d +  81920 * 2, gt,   0, h1,   64, s128);
    phase6_kernel<128,  5, 64><<<G8, 128>>>(v, 3840,  640, w1d +  90112 * 2, gt,  64, h1,  256, s128);
    phase6_kernel< 64,  7, 32><<<G8, 128>>>(v, 3840, 1280, w1d +  98304 * 2, gt, 128, h1,  576, s64);
    phase6_kernel< 64,  9, 32><<<G8, 128>>>(v, 3840, 1728, w1d + 100352 * 2, gt, 160, h1,  800, s64);
    phase6_kernel< 64, 11, 32><<<G8, 128>>>(v, 3840, 2304, w1d + 102400 * 2, gt, 192, h1, 1088, s64);
    phase6_kernel< 64, 13, 32><<<G8, 128>>>(v, 3840, 3008, w1d + 104448 * 2, gt, 224, h1, 1440, s64);

    // ---- layer 2: h1 -> h2
    gate_kernel<64><<<G32, 160>>>(h1, HD, w2d, w2d + 4096 * 2, h2, gt, s64);
    phase6_kernel<64,  3, 64><<<G8, 128>>>(h1, HD,   64, w2d + 20480 * 2, gt,   0, h2,   64, s64);
    phase6_kernel<64,  5, 64><<<G8, 128>>>(h1, HD,  256, w2d + 24576 * 2, gt,  64, h2,  256, s64);
    phase6_kernel<32,  7, 32><<<G8, 128>>>(h1, HD,  576, w2d + 28672 * 2, gt, 128, h2,  576, s32);
    phase6_kernel<32,  9, 32><<<G8, 128>>>(h1, HD,  800, w2d + 29696 * 2, gt, 160, h2,  800, s32);
    phase6_kernel<32, 11, 32><<<G8, 128>>>(h1, HD, 1088, w2d + 30720 * 2, gt, 192, h2, 1088, s32);
    phase6_kernel<32, 13, 32><<<G8, 128>>>(h1, HD, 1440, w2d + 31744 * 2, gt, 224, h2, 1440, s32);

    // ---- layer 3: h2 -> h1
    gate_kernel<64><<<G32, 160>>>(h2, HD, w3d, w3d + 4096 * 2, h1, gt, s64);
    phase6_kernel<64,  3, 64><<<G8, 128>>>(h2, HD,   64, w3d + 20480 * 2, gt,   0, h1,   64, s64);
    phase6_kernel<64,  5, 64><<<G8, 128>>>(h2, HD,  256, w3d + 24576 * 2, gt,  64, h1,  256, s64);
    phase6_kernel<32,  7, 32><<<G8, 128>>>(h2, HD,  576, w3d + 28672 * 2, gt, 128, h1,  576, s32);
    phase6_kernel<32,  9, 32><<<G8, 128>>>(h2, HD,  800, w3d + 29696 * 2, gt, 160, h1,  800, s32);
    phase6_kernel<32, 11, 32><<<G8, 128>>>(h2, HD, 1088, w3d + 30720 * 2, gt, 192, h1, 1088, s32);
    phase6_kernel<32, 13, 32><<<G8, 128>>>(h2, HD, 1440, w3d + 31744 * 2, gt, 224, h1, 1440, s32);

    // ---- layer 4
    layer4_kernel<<<BROWS / 8, 256>>>(h1, w4, out);
}

// round 16
// speedup vs baseline: 2.4880x; 1.4497x over previous
#include <cuda_runtime.h>
#include <stdint.h>
#include <math.h>

// ============================================================================
// EquivariantDecoder — R16: tcgen05 unusable (harness lowers via compute_103
// PTX, no 'a' features). Scalar pipeline, R10 phases + rewritten gate kernels.
//   gate2_kernel<K>: z[B,320] = x[B,:K] @ Wg[K,320] (unified dup weights,
//   divergence-free), silu(z[:,:64])->h, sigmoid(z[:,64:])->gates.
//   Geometry: NT=128, oc=tid&31 owns 5 output PAIRS (LDG.128 coalesced),
//   warp w owns row-pairs {w,w+4,w+8,w+12} (TB=32) -> 4x weight reuse.
//   phase6 / layer4 / phase-weight prep identical to the 1206us R10 kernel.
// ============================================================================

typedef unsigned long long u64;

#define BROWS 16384
#define HD    1856

__device__ __forceinline__ u64 ffma2(u64 a, u64 b, u64 c) {
    u64 d;
    asm("fma.rn.f32x2 %0, %1, %2, %3;" : "=l"(d) : "l"(a), "l"(b), "l"(c));
    return d;
}
__device__ __forceinline__ u64 pk2(float a, float b) {
    u64 r;
    asm("mov.b64 %0, {%1, %2};" : "=l"(r) : "f"(a), "f"(b));
    return r;
}
__device__ __forceinline__ float2 upk(u64 v) {
    float2 r;
    asm("mov.b64 {%0, %1}, %2;" : "=f"(r.x), "=f"(r.y) : "l"(v));
    return r;
}
__device__ __forceinline__ float sigf(float x) { return 1.0f / (1.0f + __expf(-x)); }

// ---- static device buffers (no allocation allowed) -------------------------
__device__ __align__(16) float g_h1[(size_t)BROWS * HD];
__device__ __align__(16) float g_h2[(size_t)BROWS * HD];
__device__ __align__(16) float g_gates[(size_t)BROWS * 256];
__device__ __align__(16) float g_w1d[212992];    // duplicated phase weights
__device__ __align__(16) float g_w2d[65536];
__device__ __align__(16) float g_w3d[65536];
__device__ __align__(16) float g_wg1d[163840];   // unified dup gate weights [K][320]x2
__device__ __align__(16) float g_wg2d[40960];
__device__ __align__(16) float g_wg3d[40960];

// ---- prep: duplicate phase weights (unchanged) + unified gate weights ------
__global__ void prep_kernel(const float* __restrict__ w1,
                            const float* __restrict__ w2,
                            const float* __restrict__ w3) {
    int k = blockIdx.x * 256 + threadIdx.x;
    if (k < 106496) { float v = w1[k]; g_w1d[2 * k] = v; g_w1d[2 * k + 1] = v; }
    if (k < 32768)  { float v = w2[k]; g_w2d[2 * k] = v; g_w2d[2 * k + 1] = v;
                      float u = w3[k]; g_w3d[2 * k] = u; g_w3d[2 * k + 1] = u; }
}

__global__ void prep_gate(const float* __restrict__ w1,
                          const float* __restrict__ w2,
                          const float* __restrict__ w3) {
    int id = blockIdx.x * 256 + threadIdx.x;   // grid covers 81920
    if (id < 81920) {
        int i = id / 320, o = id % 320;        // K=256 rows
        float v = (o < 64) ? w1[i * 64 + o] : w1[16384 + i * 256 + (o - 64)];
        g_wg1d[2 * id] = v; g_wg1d[2 * id + 1] = v;
    }
    if (id < 20480) {
        int i = id / 320, o = id % 320;        // K=64 rows
        float v2 = (o < 64) ? w2[i * 64 + o] : w2[4096 + i * 256 + (o - 64)];
        g_wg2d[2 * id] = v2; g_wg2d[2 * id + 1] = v2;
        float v3 = (o < 64) ? w3[i * 64 + o] : w3[4096 + i * 256 + (o - 64)];
        g_wg3d[2 * id] = v3; g_wg3d[2 * id + 1] = v3;
    }
}

// ============================================================================
// gate2_kernel<K>: divergence-free gate GEMM + activations.
//   Thread (oc, w): outputs {64j+2oc, 64j+2oc+1 : j=0..4}, row-pairs
//   {w,w+4,w+8,w+12}. j=0 -> silu to hout[:, 0:64); j>=1 -> sigmoid pairs to
//   gates (row-pair-packed u64 layout, same as phase6 consumer).
// ============================================================================
template <int K>
__global__ __launch_bounds__(128) void gate2_kernel(
    const float* __restrict__ xin, int in_dim, const float* __restrict__ wgd,
    float* __restrict__ hout, float* __restrict__ gates, float sc)
{
    constexpr int KP = K + 1;                  // odd u64 stride per row-pair
    __shared__ __align__(16) u64 sx[16 * KP];

    const int tid = threadIdx.x;
    const int oc = tid & 31;
    const int w  = tid >> 5;
    const int row0 = blockIdx.x * 32;

    // ---- load x tile: row-pairs packed into u64 lanes ----
    for (int r = 0; r < 32; r++) {
        const float4* src = (const float4*)(xin + (size_t)(row0 + r) * in_dim);
        float* dst = (float*)(sx + (r >> 1) * KP) + (r & 1);
        for (int c = tid; c < K / 4; c += 128) {
            float4 v = __ldg(src + c);
            dst[2 * (4 * c + 0)] = v.x;
            dst[2 * (4 * c + 1)] = v.y;
            dst[2 * (4 * c + 2)] = v.z;
            dst[2 * (4 * c + 3)] = v.w;
        }
    }
    __syncthreads();

    u64 acc[10][4];
#pragma unroll
    for (int a = 0; a < 10; a++)
#pragma unroll
        for (int rr = 0; rr < 4; rr++) acc[a][rr] = 0ull;

    const ulonglong2* wr = (const ulonglong2*)wgd + oc;   // row = 160 ull2
    const u64* x0 = sx + w * KP;

#pragma unroll 2
    for (int i = 0; i < K; i++) {
        ulonglong2 t0 = __ldg(wr + i * 160);
        ulonglong2 t1 = __ldg(wr + i * 160 + 32);
        ulonglong2 t2 = __ldg(wr + i * 160 + 64);
        ulonglong2 t3 = __ldg(wr + i * 160 + 96);
        ulonglong2 t4 = __ldg(wr + i * 160 + 128);
#pragma unroll
        for (int rr = 0; rr < 4; rr++) {
            u64 xv = x0[rr * 4 * KP + i];
            acc[0][rr] = ffma2(xv, t0.x, acc[0][rr]);
            acc[1][rr] = ffma2(xv, t0.y, acc[1][rr]);
            acc[2][rr] = ffma2(xv, t1.x, acc[2][rr]);
            acc[3][rr] = ffma2(xv, t1.y, acc[3][rr]);
            acc[4][rr] = ffma2(xv, t2.x, acc[4][rr]);
            acc[5][rr] = ffma2(xv, t2.y, acc[5][rr]);
            acc[6][rr] = ffma2(xv, t3.x, acc[6][rr]);
            acc[7][rr] = ffma2(xv, t3.y, acc[7][rr]);
            acc[8][rr] = ffma2(xv, t4.x, acc[8][rr]);
            acc[9][rr] = ffma2(xv, t4.y, acc[9][rr]);
        }
    }

    // ---- epilogue ----
#pragma unroll
    for (int rr = 0; rr < 4; rr++) {
        const int rp = w + 4 * rr;
        const int r0 = row0 + 2 * rp;
        // j = 0: silu scalars, outputs 2oc, 2oc+1
#pragma unroll
        for (int e = 0; e < 2; e++) {
            float2 z = upk(acc[e][rr]);
            float z0 = z.x * sc, z1 = z.y * sc;
            int o = 2 * oc + e;
            hout[(size_t)r0 * HD + o]       = z0 * sigf(z0);
            hout[(size_t)(r0 + 1) * HD + o] = z1 * sigf(z1);
        }
        // j = 1..4: sigmoid gates, row-pair-packed u64
        u64* gp = (u64*)gates + (size_t)(row0 / 2 + rp) * 256;
#pragma unroll
        for (int j = 1; j < 5; j++)
#pragma unroll
            for (int e = 0; e < 2; e++) {
                float2 z = upk(acc[2 * j + e][rr]);
                gp[64 * (j - 1) + 2 * oc + e] = pk2(sigf(z.x * sc), sigf(z.y * sc));
            }
    }
}

// ============================================================================
// phase6_kernel — identical to passing R10.
// ============================================================================
template <int MI, int NM, int MO>
__global__ __launch_bounds__(128, 8) void phase6_kernel(
    const float* __restrict__ xin, int in_dim, int in_off,
    const float* __restrict__ wd, const float* __restrict__ gates,
    int goff, float* __restrict__ hout, int hoff, float sc)
{
    constexpr int OPT = MO / 32;
    constexpr int FEATS = MI * NM;
    constexpr int NMp = (NM + 1) & ~1;
    constexpr int ROWU = MI * NMp;
    constexpr int OUTLEN = MO * NM;

    __shared__ __align__(16) u64 sx[4 * ROWU];
    float* sxf = (float*)sx;

    const int tid = threadIdx.x;
    const int oc = tid & 31;
    const int rp = tid >> 5;
    const int row0 = blockIdx.x * 8;

    for (int r = 0; r < 8; r++) {
        const float4* src = (const float4*)(xin + (size_t)(row0 + r) * in_dim + in_off);
        float* dst = (float*)(sx + (r >> 1) * ROWU) + (r & 1);
        for (int c = tid; c < FEATS / 4; c += 128) {
            float4 v = __ldg(src + c);
            int f = 4 * c;
#pragma unroll
            for (int q = 0; q < 4; q++) {
                int i = (f + q) / NM;
                int m = (f + q) - i * NM;
                dst[2 * (i * NMp + m)] = (&v.x)[q];
            }
        }
    }
    __syncthreads();

    u64 acc[OPT][NM];
#pragma unroll
    for (int j = 0; j < OPT; j++)
#pragma unroll
        for (int m = 0; m < NM; m++) acc[j][m] = 0ull;

    const u64* xp = sx + rp * ROWU;

    if (OPT == 2) {
        const ulonglong2* wr = (const ulonglong2*)wd + oc;
#pragma unroll 2
        for (int i = 0; i < MI; i++) {
            ulonglong2 t = __ldg(wr + i * 32);
            const u64* xb = xp + i * NMp;
#pragma unroll
            for (int m = 0; m + 1 < NM; m += 2) {
                ulonglong2 p = *(const ulonglong2*)(xb + m);
                acc[0][m]     = ffma2(p.x, t.x, acc[0][m]);
                acc[1][m]     = ffma2(p.x, t.y, acc[1][m]);
                acc[0][m + 1] = ffma2(p.y, t.x, acc[0][m + 1]);
                acc[1][m + 1] = ffma2(p.y, t.y, acc[1][m + 1]);
            }
            {
                u64 xv = xb[NM - 1];
                acc[0][NM - 1] = ffma2(xv, t.x, acc[0][NM - 1]);
                acc[1][NM - 1] = ffma2(xv, t.y, acc[1][NM - 1]);
            }
        }
    } else {
        const u64* wr = (const u64*)wd + oc;
#pragma unroll 2
        for (int i = 0; i < MI; i++) {
            u64 t = __ldg(wr + i * 32);
            const u64* xb = xp + i * NMp;
#pragma unroll
            for (int m = 0; m + 1 < NM; m += 2) {
                ulonglong2 p = *(const ulonglong2*)(xb + m);
                acc[0][m]     = ffma2(p.x, t, acc[0][m]);
                acc[0][m + 1] = ffma2(p.y, t, acc[0][m + 1]);
            }
            acc[0][NM - 1] = ffma2(xb[NM - 1], t, acc[0][NM - 1]);
        }
    }

    u64 g[OPT];
    const u64* gp = (const u64*)gates + (size_t)(row0 / 2 + rp) * 256 + goff + oc * OPT;
#pragma unroll
    for (int j = 0; j < OPT; j++) g[j] = __ldg(gp + j);

    __syncthreads();

#pragma unroll
    for (int j = 0; j < OPT; j++) {
        float2 gg = upk(g[j]);
#pragma unroll
        for (int m = 0; m < NM; m++) {
            float2 a = upk(acc[j][m]);
            int col = (oc * OPT + j) * NM + m;
            sxf[(2 * rp) * OUTLEN + col]     = a.x * sc * gg.x;
            sxf[(2 * rp + 1) * OUTLEN + col] = a.y * sc * gg.y;
        }
    }
    __syncthreads();

    for (int r = 0; r < 8; r++) {
        float4* d = (float4*)(hout + (size_t)(row0 + r) * HD + hoff);
        const float4* s = (const float4*)(sxf + r * OUTLEN);
        for (int c = tid; c < OUTLEN / 4; c += 128) d[c] = s[c];
    }
}

// ============================================================================
// layer4 — unchanged.
// ============================================================================
__global__ __launch_bounds__(256) void layer4_kernel(
    const float* __restrict__ h, const float* __restrict__ w4,
    float* __restrict__ out)
{
    const int warp = threadIdx.x >> 5;
    const int lane = threadIdx.x & 31;
    const int row  = blockIdx.x * 8 + warp;

    const float* hr = h + (size_t)row * HD;

    const int MI[7]   = {64, 64, 64, 32, 32, 32, 32};
    const int XOFF[7] = {0, 64, 256, 576, 800, 1088, 1440};
    const int WOFF[7] = {0, 64, 128, 192, 224, 256, 288};
    const int OOFF[7] = {0, 1, 4, 9, 16, 25, 36};

#pragma unroll
    for (int l = 0; l < 7; l++) {
        const int nm = 2 * l + 1;
        const int mi = MI[l];
        const float sc = rsqrtf((float)mi);
        for (int m = 0; m < nm; m++) {
            float s = 0.0f;
            for (int i = lane; i < mi; i += 32)
                s += hr[XOFF[l] + i * nm + m] * __ldg(w4 + WOFF[l] + i);
#pragma unroll
            for (int off = 16; off; off >>= 1)
                s += __shfl_xor_sync(0xFFFFFFFFu, s, off);
            if (lane == 0)
                out[(size_t)row * 49 + OOFF[l] + m] = s * sc;
        }
    }
}

// ---- launch ----------------------------------------------------------------
extern "C" void kernel_launch(void* const* d_in, const int* in_sizes, int n_in,
                              void* d_out, int out_size)
{
    const float* v  = (const float*)d_in[0];
    const float* w1 = (const float*)d_in[1];
    const float* w2 = (const float*)d_in[2];
    const float* w3 = (const float*)d_in[3];
    const float* w4 = (const float*)d_in[4];
    float* out = (float*)d_out;

    float *h1, *h2, *gt, *w1d, *w2d, *w3d, *wg1, *wg2, *wg3;
    cudaGetSymbolAddress((void**)&h1,  g_h1);
    cudaGetSymbolAddress((void**)&h2,  g_h2);
    cudaGetSymbolAddress((void**)&gt,  g_gates);
    cudaGetSymbolAddress((void**)&w1d, g_w1d);
    cudaGetSymbolAddress((void**)&w2d, g_w2d);
    cudaGetSymbolAddress((void**)&w3d, g_w3d);
    cudaGetSymbolAddress((void**)&wg1, g_wg1d);
    cudaGetSymbolAddress((void**)&wg2, g_wg2d);
    cudaGetSymbolAddress((void**)&wg3, g_wg3d);

    const float s256 = 1.0f / sqrtf(256.0f);
    const float s128 = 1.0f / sqrtf(128.0f);
    const float s64  = 1.0f / sqrtf(64.0f);
    const float s32  = 1.0f / sqrtf(32.0f);

    prep_kernel<<<416, 256>>>(w1, w2, w3);
    prep_gate<<<320, 256>>>(w1, w2, w3);

    const int G32 = BROWS / 32;   // 512  (gate kernels)
    const int G8  = BROWS / 8;    // 2048 (phase kernels)

    // ---- layer 1: v(3840) -> h1
    gate2_kernel<256><<<G32, 128>>>(v, 3840, wg1, h1, gt, s256);
    phase6_kernel<128,  3, 64><<<G8, 128>>>(v, 3840,  256, w1d +  81920 * 2, gt,   0, h1,   64, s128);
    phase6_kernel<128,  5, 64><<<G8, 128>>>(v, 3840,  640, w1d +  90112 * 2, gt,  64, h1,  256, s128);
    phase6_kernel< 64,  7, 32><<<G8, 128>>>(v, 3840, 1280, w1d +  98304 * 2, gt, 128, h1,  576, s64);
    phase6_kernel< 64,  9, 32><<<G8, 128>>>(v, 3840, 1728, w1d + 100352 * 2, gt, 160, h1,  800, s64);
    phase6_kernel< 64, 11, 32><<<G8, 128>>>(v, 3840, 2304, w1d + 102400 * 2, gt, 192, h1, 1088, s64);
    phase6_kernel< 64, 13, 32><<<G8, 128>>>(v, 3840, 3008, w1d + 104448 * 2, gt, 224, h1, 1440, s64);

    // ---- layer 2: h1 -> h2
    gate2_kernel<64><<<G32, 128>>>(h1, HD, wg2, h2, gt, s64);
    phase6_kernel<64,  3, 64><<<G8, 128>>>(h1, HD,   64, w2d + 20480 * 2, gt,   0, h2,   64, s64);
    phase6_kernel<64,  5, 64><<<G8, 128>>>(h1, HD,  256, w2d + 24576 * 2, gt,  64, h2,  256, s64);
    phase6_kernel<32,  7, 32><<<G8, 128>>>(h1, HD,  576, w2d + 28672 * 2, gt, 128, h2,  576, s32);
    phase6_kernel<32,  9, 32><<<G8, 128>>>(h1, HD,  800, w2d + 29696 * 2, gt, 160, h2,  800, s32);
    phase6_kernel<32, 11, 32><<<G8, 128>>>(h1, HD, 1088, w2d + 30720 * 2, gt, 192, h2, 1088, s32);
    phase6_kernel<32, 13, 32><<<G8, 128>>>(h1, HD, 1440, w2d + 31744 * 2, gt, 224, h2, 1440, s32);

    // ---- layer 3: h2 -> h1
    gate2_kernel<64><<<G32, 128>>>(h2, HD, wg3, h1, gt, s64);
    phase6_kernel<64,  3, 64><<<G8, 128>>>(h2, HD,   64, w3d + 20480 * 2, gt,   0, h1,   64, s64);
    phase6_kernel<64,  5, 64><<<G8, 128>>>(h2, HD,  256, w3d + 24576 * 2, gt,  64, h1,  256, s64);
    phase6_kernel<32,  7, 32><<<G8, 128>>>(h2, HD,  576, w3d + 28672 * 2, gt, 128, h1,  576, s32);
    phase6_kernel<32,  9, 32><<<G8, 128>>>(h2, HD,  800, w3d + 29696 * 2, gt, 160, h1,  800, s32);
    phase6_kernel<32, 11, 32><<<G8, 128>>>(h2, HD, 1088, w3d + 30720 * 2, gt, 192, h1, 1088, s32);
    phase6_kernel<32, 13, 32><<<G8, 128>>>(h2, HD, 1440, w3d + 31744 * 2, gt, 224, h1, 1440, s32);

    // ---- layer 4
    layer4_kernel<<<BROWS / 8, 256>>>(h1, w4, out);
}